// round 17
// baseline (speedup 1.0000x reference)
#include <cuda_runtime.h>
#include <cuda_bf16.h>
#include <cstdint>

// ---------------- problem constants ----------------
#define SS    1024
#define INW   32
#define HH    128
#define NTHR  256          // 8 warps; warp w owns all 4 gate types of units w*16..w*16+15
#define NBLK  128          // 4 batch rows per CTA
#define KTOT  160          // 128 h + 32 x
#define NKT   10           // k16 tiles (bf16 set)
#define NKQ   5            // k32 tiles (fp8 set)
#define BST   168          // bf16 B staging stride in bf16 elems (conflict-free)
// bf16 staging: 8 rows; rows 0..3 = hi(batch 0..3), rows 4..7 = lo(batch 0..3)
#define BSTAGE_BYTES (8 * BST * 2)      // 2688, x2 ping-pong
#define B8ST  176          // fp8 staging stride in bytes
#define B8BUF (8 * B8ST)   // 1408, x2 ping-pong (rows 4..7 stay zero)
// scale split: product (W_lo*16) * (h*2^-4) has scale 1 -> same accumulators
#define SC_A  16.0f
#define SC_B  0.0625f

#define OFF_A8     0
#define A8_BYTES   (8 * 4 * NKQ * 32 * 16)     // 81920: W_lo e4m3 fragments (x16)
#define OFF_B      A8_BYTES                     // 81920: 2 ping-pong bf16 staging
#define OFF_B8     (OFF_B + 2 * BSTAGE_BYTES)  // 87296: 2 ping-pong fp8 staging
#define OFF_LRED   (OFF_B8 + 2 * B8BUF)        // 90112
#define SMEM_BYTES (OFF_LRED + 256)            // 90368

// ---------------- helpers ----------------
__device__ __forceinline__ unsigned short bf16_bits(float v) {
    __nv_bfloat16 b = __float2bfloat16(v);
    return *reinterpret_cast<unsigned short*>(&b);
}
__device__ __forceinline__ float bf16_val(unsigned short s) {
    __nv_bfloat16 b = *reinterpret_cast<__nv_bfloat16*>(&s);
    return __bfloat162float(b);
}
__device__ __forceinline__ void split_bf16(float w, unsigned short& hi, unsigned short& lo) {
    hi = bf16_bits(w);
    lo = bf16_bits(w - bf16_val(hi));
}
__device__ __forceinline__ uint32_t pack2(unsigned short a16, unsigned short b16) {
    return (uint32_t)a16 | ((uint32_t)b16 << 16);
}
// pack two floats -> e4m3x2; FIRST operand lands in the UPPER byte
__device__ __forceinline__ unsigned short cvt_e4m3x2(float hi_byte, float lo_byte) {
    unsigned short r;
    asm("cvt.rn.satfinite.e4m3x2.f32 %0, %1, %2;" : "=h"(r) : "f"(hi_byte), "f"(lo_byte));
    return r;
}
__device__ __forceinline__ uint32_t pack4_e4m3(float k0, float k1, float k2, float k3) {
    return (uint32_t)cvt_e4m3x2(k1, k0) | ((uint32_t)cvt_e4m3x2(k3, k2) << 16);
}
__device__ __forceinline__ void mma_bf16(float& d0, float& d1, float& d2, float& d3,
                                         uint32_t a0, uint32_t a1, uint32_t a2, uint32_t a3,
                                         uint32_t b0, uint32_t b1) {
    asm volatile(
        "mma.sync.aligned.m16n8k16.row.col.f32.bf16.bf16.f32 "
        "{%0,%1,%2,%3}, {%4,%5,%6,%7}, {%8,%9}, {%0,%1,%2,%3};"
        : "+f"(d0), "+f"(d1), "+f"(d2), "+f"(d3)
        : "r"(a0), "r"(a1), "r"(a2), "r"(a3), "r"(b0), "r"(b1));
}
__device__ __forceinline__ void mma_fp8(float& d0, float& d1, float& d2, float& d3,
                                        uint32_t a0, uint32_t a1, uint32_t a2, uint32_t a3,
                                        uint32_t b0, uint32_t b1) {
    asm volatile(
        "mma.sync.aligned.m16n8k32.row.col.f32.e4m3.e4m3.f32 "
        "{%0,%1,%2,%3}, {%4,%5,%6,%7}, {%8,%9}, {%0,%1,%2,%3};"
        : "+f"(d0), "+f"(d1), "+f"(d2), "+f"(d3)
        : "r"(a0), "r"(a1), "r"(a2), "r"(a3), "r"(b0), "r"(b1));
}
__device__ __forceinline__ float sigmoid_f(float v) {
    return __fdividef(1.0f, 1.0f + __expf(-v));
}
__device__ __forceinline__ float tanh_f(float v) {
    return 1.0f - __fdividef(2.0f, __expf(2.0f * v) + 1.0f);
}

__global__ void __launch_bounds__(NTHR, 1)
lstm_mma_kernel(const float* __restrict__ x,     // [B,S,IN]
                const float* __restrict__ Wih,   // [4H,IN]
                const float* __restrict__ Whh,   // [4H,H]
                const float* __restrict__ bih,   // [4H]
                const float* __restrict__ bhh,   // [4H]
                const float* __restrict__ Wlin,  // [1, S*H]
                const float* __restrict__ blin,  // [1]
                float* __restrict__ out)         // [B,1]
{
    extern __shared__ char smc[];
    float* smf = reinterpret_cast<float*>(smc);
    const int tid  = threadIdx.x;
    const int wid  = tid >> 5;
    const int lane = tid & 31;
    const int b0   = blockIdx.x * 4;

    // ---------------- prologue ----------------
    for (int i = tid; i < (2 * BSTAGE_BYTES) / 4; i += NTHR)
        reinterpret_cast<uint32_t*>(smc + OFF_B)[i] = 0;
    for (int i = tid; i < (2 * B8BUF) / 4; i += NTHR)
        reinterpret_cast<uint32_t*>(smc + OFF_B8)[i] = 0;
    if (tid < 64) smf[(OFF_LRED >> 2) + tid] = 0.0f;

    // Gate-type mapping (R15): warp w, m-tile mt = gate TYPE mt of units w*16..+15.
    // W_hi bf16 fragments -> registers (4 mt x 10 kt x 4 = 160 regs).
    uint32_t wa[4][NKT][4];
    {
        const int r  = lane >> 2;
        const int kc = (lane & 3) * 2;
        #pragma unroll
        for (int mt = 0; mt < 4; mt++) {
            #pragma unroll
            for (int kt = 0; kt < NKT; kt++) {
                #pragma unroll
                for (int rg = 0; rg < 4; rg++) {
                    int g = mt * 128 + wid * 16 + r + ((rg & 1) ? 8 : 0);
                    int k = kt * 16 + kc + ((rg & 2) ? 8 : 0);
                    float2 w2;
                    if (k < HH) w2 = *reinterpret_cast<const float2*>(Whh + (size_t)g * HH + k);
                    else        w2 = *reinterpret_cast<const float2*>(Wih + (size_t)g * INW + (k - HH));
                    wa[mt][kt][rg] = pack2(bf16_bits(w2.x), bf16_bits(w2.y));
                }
            }
        }
    }
    // W_lo e4m3 fragments (x16) -> smem A8, m16n8k32 A layout
    {
        const int r   = lane >> 2;
        const int kc4 = (lane & 3) * 4;
        #pragma unroll
        for (int mt = 0; mt < 4; mt++) {
            #pragma unroll
            for (int kq = 0; kq < NKQ; kq++) {
                uint32_t frag[4];
                #pragma unroll
                for (int rg = 0; rg < 4; rg++) {
                    int g = mt * 128 + wid * 16 + r + ((rg & 1) ? 8 : 0);
                    int k = kq * 32 + kc4 + ((rg & 2) ? 16 : 0);
                    float4 w4;
                    if (k < HH) w4 = *reinterpret_cast<const float4*>(Whh + (size_t)g * HH + k);
                    else        w4 = *reinterpret_cast<const float4*>(Wih + (size_t)g * INW + (k - HH));
                    float l0 = (w4.x - bf16_val(bf16_bits(w4.x))) * SC_A;
                    float l1 = (w4.y - bf16_val(bf16_bits(w4.y))) * SC_A;
                    float l2 = (w4.z - bf16_val(bf16_bits(w4.z))) * SC_A;
                    float l3 = (w4.w - bf16_val(bf16_bits(w4.w))) * SC_A;
                    frag[rg] = pack4_e4m3(l0, l1, l2, l3);
                }
                *reinterpret_cast<uint4*>(smc + OFF_A8 +
                    (size_t)((((wid * 4 + mt) * NKQ + kq) * 32 + lane) * 16))
                    = make_uint4(frag[0], frag[1], frag[2], frag[3]);
            }
        }
    }

    // ew role (all 32 lanes): unit u_sel, batch rows n, n+1
    const int  u_sel = wid * 16 + (lane >> 2) + ((lane & 2) ? 8 : 0);
    const int  n     = 2 * (lane & 1);
    const bool hiD   = (lane & 2) == 0;    // use d0/d1 if true else d2/d3
    float bgt[4];
    #pragma unroll
    for (int mt = 0; mt < 4; mt++)
        bgt[mt] = bih[mt * 128 + u_sel] + bhh[mt * 128 + u_sel];
    float cA = 0.0f, cB = 0.0f;
    float linA = 0.0f, linB = 0.0f;

    __syncthreads();                       // staging zero complete
    if (tid < 64) {                        // x(t=0) into buf 0 (bf16 + fp8)
        int row = tid >> 4, i0 = (tid & 15) * 2;
        float2 xv = *reinterpret_cast<const float2*>(
            x + ((size_t)(b0 + row) * SS + 0) * INW + i0);
        unsigned short h0, l0, h1, l1;
        split_bf16(xv.x, h0, l0);
        split_bf16(xv.y, h1, l1);
        *reinterpret_cast<uint32_t*>(smc + OFF_B + (size_t)(row * BST + HH + i0) * 2)
            = pack2(h0, h1);
        *reinterpret_cast<uint32_t*>(smc + OFF_B + (size_t)((row + 4) * BST + HH + i0) * 2)
            = pack2(l0, l1);
        *reinterpret_cast<unsigned short*>(smc + OFF_B8 + row * B8ST + HH + i0)
            = cvt_e4m3x2(xv.y * SC_B, xv.x * SC_B);
    }
    __syncthreads();

    const int bn  = lane >> 2;             // B fragment column 0..7
    const int bk  = (lane & 3) * 2;
    const int bk4 = (lane & 3) * 4;

    // ---------------- main recurrence ----------------
    #pragma unroll 1
    for (int t = 0; t < SS; t++) {
        const float wl = __ldg(Wlin + (size_t)t * HH + u_sel);
        float2 xv = make_float2(0.0f, 0.0f);
        if (tid < 64) {
            int row = tid >> 4, i0 = (tid & 15) * 2;
            int tn = (t + 1 < SS) ? (t + 1) : (SS - 1);
            xv = *reinterpret_cast<const float2*>(
                x + ((size_t)(b0 + row) * SS + tn) * INW + i0);
        }

        const char* bbase  = smc + OFF_B  + (size_t)(t & 1) * BSTAGE_BYTES;
        const char* bbase8 = smc + OFF_B8 + (size_t)(t & 1) * B8BUF;

        // === MMA phase ===
        float d0[4], d1[4], d2[4], d3[4];
        #pragma unroll
        for (int mt = 0; mt < 4; mt++) { d0[mt] = 0.f; d1[mt] = 0.f; d2[mt] = 0.f; d3[mt] = 0.f; }

        // set 1: bf16 W_hi x [B_hi | B_lo]  (hi*hi in cols 0-3, hi*lo in cols 4-7)
        #pragma unroll
        for (int kt = 0; kt < NKT; kt++) {
            const char* bb = bbase + (size_t)((bn * BST + kt * 16 + bk) * 2);
            uint32_t bb0 = *reinterpret_cast<const uint32_t*>(bb);
            uint32_t bb1 = *reinterpret_cast<const uint32_t*>(bb + 16);
            #pragma unroll
            for (int mt = 0; mt < 4; mt++)
                mma_bf16(d0[mt], d1[mt], d2[mt], d3[mt],
                         wa[mt][kt][0], wa[mt][kt][1], wa[mt][kt][2], wa[mt][kt][3],
                         bb0, bb1);
        }
        // set 2: fp8 (W_lo*16) x (B8_hi*2^-4) -> scale 1, SAME accumulators.
        // B8 cols 4-7 are zero: cols 4-7 (hi*lo partials) unchanged.
        #pragma unroll
        for (int kq = 0; kq < NKQ; kq++) {
            const char* bb = bbase8 + (size_t)(bn * B8ST + kq * 32 + bk4);
            uint32_t b80 = *reinterpret_cast<const uint32_t*>(bb);
            uint32_t b81 = *reinterpret_cast<const uint32_t*>(bb + 16);
            #pragma unroll
            for (int mt = 0; mt < 4; mt++) {
                const uint4 a8 = *reinterpret_cast<const uint4*>(smc + OFF_A8 +
                    (size_t)((((wid * 4 + mt) * NKQ + kq) * 32 + lane) * 16));
                mma_fp8(d0[mt], d1[mt], d2[mt], d3[mt],
                        a8.x, a8.y, a8.z, a8.w, b80, b81);
            }
        }

        // cross-column reduce: preact = cols n + n+4 (hi*hi + lo*hi + hi*lo)
        #pragma unroll
        for (int mt = 0; mt < 4; mt++) {
            d0[mt] += __shfl_xor_sync(0xffffffffu, d0[mt], 2);
            d1[mt] += __shfl_xor_sync(0xffffffffu, d1[mt], 2);
            d2[mt] += __shfl_xor_sync(0xffffffffu, d2[mt], 2);
            d3[mt] += __shfl_xor_sync(0xffffffffu, d3[mt], 2);
        }

        // === in-register elementwise: 2 cells per lane ===
        char* nbase  = smc + OFF_B  + (size_t)((t + 1) & 1) * BSTAGE_BYTES;
        char* nbase8 = smc + OFF_B8 + (size_t)((t + 1) & 1) * B8BUF;
        {
            float pA[4], pB[4];
            #pragma unroll
            for (int mt = 0; mt < 4; mt++) {
                pA[mt] = (hiD ? d0[mt] : d2[mt]) + bgt[mt];
                pB[mt] = (hiD ? d1[mt] : d3[mt]) + bgt[mt];
            }
            float ivA = sigmoid_f(pA[0]);
            float fvA = sigmoid_f(pA[1]);
            float gvA = tanh_f(pA[2]);
            float ovA = sigmoid_f(pA[3]);
            cA = fmaf(fvA, cA, ivA * gvA);
            float hvA = ovA * tanh_f(cA);
            linA = fmaf(hvA, wl, linA);

            float ivB = sigmoid_f(pB[0]);
            float fvB = sigmoid_f(pB[1]);
            float gvB = tanh_f(pB[2]);
            float ovB = sigmoid_f(pB[3]);
            cB = fmaf(fvB, cB, ivB * gvB);
            float hvB = ovB * tanh_f(cB);
            linB = fmaf(hvB, wl, linB);

            unsigned short hA, lA, hB, lB;
            split_bf16(hvA, hA, lA);
            split_bf16(hvB, hB, lB);
            *reinterpret_cast<unsigned short*>(nbase + (size_t)(n * BST + u_sel) * 2)       = hA;
            *reinterpret_cast<unsigned short*>(nbase + (size_t)((n + 4) * BST + u_sel) * 2) = lA;
            *reinterpret_cast<unsigned short*>(nbase + (size_t)((n + 1) * BST + u_sel) * 2) = hB;
            *reinterpret_cast<unsigned short*>(nbase + (size_t)((n + 5) * BST + u_sel) * 2) = lB;
            // fp8 staging (h * 2^-4); single-byte stores
            *reinterpret_cast<unsigned char*>(nbase8 + (size_t)(n * B8ST + u_sel))
                = (unsigned char)cvt_e4m3x2(0.0f, hvA * SC_B);
            *reinterpret_cast<unsigned char*>(nbase8 + (size_t)((n + 1) * B8ST + u_sel))
                = (unsigned char)cvt_e4m3x2(0.0f, hvB * SC_B);
        }
        // x(t+1) into next buffers
        if (tid < 64) {
            int row = tid >> 4, i0 = (tid & 15) * 2;
            unsigned short h0, l0, h1, l1;
            split_bf16(xv.x, h0, l0);
            split_bf16(xv.y, h1, l1);
            *reinterpret_cast<uint32_t*>(nbase + (size_t)(row * BST + HH + i0) * 2)
                = pack2(h0, h1);
            *reinterpret_cast<uint32_t*>(nbase + (size_t)((row + 4) * BST + HH + i0) * 2)
                = pack2(l0, l1);
            *reinterpret_cast<unsigned short*>(nbase8 + (size_t)(row * B8ST + HH + i0))
                = cvt_e4m3x2(xv.y * SC_B, xv.x * SC_B);
        }
        __syncthreads();                  // single barrier per step
    }

    // ---------------- epilogue ----------------
    #pragma unroll
    for (int off = 2; off <= 16; off <<= 1) {
        linA += __shfl_xor_sync(0xffffffffu, linA, off);
        linB += __shfl_xor_sync(0xffffffffu, linB, off);
    }
    if (lane < 2) {
        smf[(OFF_LRED >> 2) + wid * 4 + 2 * lane]     = linA;   // row 2*lane
        smf[(OFF_LRED >> 2) + wid * 4 + 2 * lane + 1] = linB;   // row 2*lane+1
    }
    __syncthreads();
    if (tid < 4) {
        float s = blin[0];
        #pragma unroll
        for (int w = 0; w < 8; w++) s += smf[(OFF_LRED >> 2) + w * 4 + tid];
        out[b0 + tid] = s;
    }
}

extern "C" void kernel_launch(void* const* d_in, const int* in_sizes, int n_in,
                              void* d_out, int out_size)
{
    const float* x    = (const float*)d_in[0];
    const float* Wih  = (const float*)d_in[1];
    const float* Whh  = (const float*)d_in[2];
    const float* bih  = (const float*)d_in[3];
    const float* bhh  = (const float*)d_in[4];
    const float* Wlin = (const float*)d_in[5];
    const float* blin = (const float*)d_in[6];
    float* out = (float*)d_out;

    cudaFuncSetAttribute(lstm_mma_kernel,
                         cudaFuncAttributeMaxDynamicSharedMemorySize, SMEM_BYTES);
    lstm_mma_kernel<<<NBLK, NTHR, SMEM_BYTES>>>(x, Wih, Whh, bih, bhh, Wlin, blin, out);
}